// round 3
// baseline (speedup 1.0000x reference)
#include <cuda_runtime.h>
#include <math.h>

#define NB 8
#define NT 128
#define NU 64
#define NU1 65
#define NV 512

// ---------------- device scratch (no allocations allowed) ----------------
__device__ float g_Et[NB * NT * NV];    // exp(trans - rowmax)   2 MB
__device__ float g_Ep[NB * NU1 * NV];   // exp(pred  - rowmax)   1 MB
__device__ float g_mt[NB * NT];
__device__ float g_mp[NB * NU1];
__device__ float g_lpb[NB * NT * NU1];  // log P(blank)  at (b,t,u)
__device__ float g_lpl[NB * NT * NU];   // log P(label u) at (b,t,u)
__device__ float g_cost[NB];

// ---------------- kernel 1: row max + exp (vectorized) ----------------
// rows [0, NB*NT)        -> trans rows
// rows [NB*NT, +NB*NU1)  -> pred rows
__global__ void __launch_bounds__(128)
rnnt_prep_kernel(const float* __restrict__ trans,
                 const float* __restrict__ pred) {
    int row = blockIdx.x;
    const float* src;
    float* dst;
    float* mdst;
    if (row < NB * NT) {
        src = trans + (size_t)row * NV;
        dst = g_Et + (size_t)row * NV;
        mdst = g_mt + row;
    } else {
        int r = row - NB * NT;
        src = pred + (size_t)r * NV;
        dst = g_Ep + (size_t)r * NV;
        mdst = g_mp + r;
    }
    int tid = threadIdx.x;  // 128 threads, 4 floats each via float4
    float4 v = ((const float4*)src)[tid];
    float m = fmaxf(fmaxf(v.x, v.y), fmaxf(v.z, v.w));
#pragma unroll
    for (int o = 16; o > 0; o >>= 1)
        m = fmaxf(m, __shfl_xor_sync(0xffffffffu, m, o));
    __shared__ float sm[4];
    if ((tid & 31) == 0) sm[tid >> 5] = m;
    __syncthreads();
    m = fmaxf(fmaxf(sm[0], sm[1]), fmaxf(sm[2], sm[3]));
    if (tid == 0) *mdst = m;
    float4 e;
    e.x = __expf(v.x - m);
    e.y = __expf(v.y - m);
    e.z = __expf(v.z - m);
    e.w = __expf(v.w - m);
    ((float4*)dst)[tid] = e;
}

// ---------------- kernel 2: batched Et @ Ep^T + epilogue ----------------
// S[b,t,u] = dot(Et[b,t,:], Ep[b,u,:]);  lse = log S + mt + mp
// lp_blank = trans[b,t,0] + pred[b,u,0] - lse
// lp_lab   = trans[b,t,lab] + pred[b,u,lab] - lse   (u < NU)
#define TK 32
__global__ void __launch_bounds__(256)
rnnt_joint_kernel(const float* __restrict__ trans,
                  const float* __restrict__ pred,
                  const int* __restrict__ labels) {
    int b  = blockIdx.z;
    int t0 = blockIdx.y * 16;
    int u0 = blockIdx.x * 16;

    __shared__ float As[16][TK];      // Et tile
    __shared__ float Bs[16][TK + 1];  // Ep tile (padded)

    int tid = threadIdx.x;            // 256 threads
    int tx = tid & 15;                // u within tile
    int ty = tid >> 4;                // t within tile

    const float* __restrict__ Et = g_Et + ((size_t)(b * NT + t0)) * NV;
    const float* __restrict__ Ep = g_Ep + ((size_t)(b * NU1)) * NV;

    float acc = 0.f;
    for (int k0 = 0; k0 < NV; k0 += TK) {
#pragma unroll
        for (int i = 0; i < 2; i++) {
            int idx = tid + i * 256;
            int r = idx >> 5;
            int c = idx & 31;
            As[r][c] = Et[(size_t)r * NV + k0 + c];
            int uu = u0 + r;
            Bs[r][c] = (uu < NU1) ? Ep[(size_t)uu * NV + k0 + c] : 0.f;
        }
        __syncthreads();
#pragma unroll
        for (int k = 0; k < TK; k++) acc += As[ty][k] * Bs[tx][k];
        __syncthreads();
    }

    int t = t0 + ty;
    int u = u0 + tx;
    if (u < NU1) {
        float lse = logf(acc) + g_mt[b * NT + t] + g_mp[b * NU1 + u];
        const float* trow = trans + ((size_t)(b * NT + t)) * NV;
        const float* prow = pred + ((size_t)(b * NU1 + u)) * NV;
        g_lpb[(b * NT + t) * NU1 + u] = trow[0] + prow[0] - lse;
        if (u < NU) {
            int lab = labels[b * NU + u];
            g_lpl[(b * NT + t) * NU + u] = trow[lab] + prow[lab] - lse;
        }
    }
}

// ---------------- kernel 3: per-batch alpha DP (anti-diagonal wavefront) --
__device__ __forceinline__ float lae(float a, float c) {
    float mx = fmaxf(a, c);
    float mn = fminf(a, c);
    return mx + log1pf(__expf(mn - mx));
}

__global__ void __launch_bounds__(96)
rnnt_dp_kernel(const int* __restrict__ act_lens,
               const int* __restrict__ label_lens) {
    int b = blockIdx.x;
    __shared__ float alpha[NT][NU1];  // 33280 B
    __shared__ float scan[NU1];

    const float* __restrict__ LPB = g_lpb + (size_t)b * NT * NU1;
    const float* __restrict__ LPL = g_lpl + (size_t)b * NT * NU;

    int u = threadIdx.x;  // 96 threads; u < NU1 active for DP

    // t = 0 row: alpha[0][u] = cumsum_{u'<u} lp_lab[0][u']
    // (inclusive Hillis-Steele scan over the shifted sequence)
    if (u < NU1) scan[u] = (u == 0) ? 0.f : LPL[u - 1];
    __syncthreads();
    for (int o = 1; o < NU1; o <<= 1) {
        float add = 0.f;
        if (u < NU1 && u >= o) add = scan[u - o];
        __syncthreads();
        if (u < NU1) scan[u] += add;
        __syncthreads();
    }
    if (u < NU1) alpha[0][u] = scan[u];
    __syncthreads();

    // diagonals d = t + u, t in [1, NT-1], u in [0, NU1-1]
    for (int d = 1; d <= (NT - 1) + (NU1 - 1); d++) {
        if (u < NU1) {
            int t = d - u;
            if (t >= 1 && t <= NT - 1) {
                float a = alpha[t - 1][u] + LPB[(t - 1) * NU1 + u];
                if (u > 0) {
                    float c = alpha[t][u - 1] + LPL[t * NU + (u - 1)];
                    a = lae(a, c);
                }
                alpha[t][u] = a;
            }
        }
        __syncthreads();
    }

    if (u == 0) {
        int te = act_lens[b] - 1;
        int ue = label_lens[b];
        float ll = alpha[te][ue] + LPB[te * NU1 + ue];
        g_cost[b] = -ll;
    }
}

// ---------------- kernel 4: deterministic final sum ----------------
__global__ void __launch_bounds__(32)
rnnt_finish_kernel(float* __restrict__ out) {
    if (threadIdx.x == 0) {
        float s = 0.f;
        for (int b = 0; b < NB; b++) s += g_cost[b];
        out[0] = s;
    }
}

extern "C" void kernel_launch(void* const* d_in, const int* in_sizes, int n_in,
                              void* d_out, int out_size) {
    const float* trans   = (const float*)d_in[0];  // (B,T,V)
    const float* pred    = (const float*)d_in[1];  // (B,U1,V)
    const int*   labels  = (const int*)d_in[2];    // (B,U)
    const int*   act_l   = (const int*)d_in[3];    // (B,)
    const int*   label_l = (const int*)d_in[4];    // (B,)
    float*       out     = (float*)d_out;

    rnnt_prep_kernel<<<NB * NT + NB * NU1, 128>>>(trans, pred);

    dim3 jg((NU1 + 15) / 16, NT / 16, NB);  // (5, 8, 8)
    rnnt_joint_kernel<<<jg, 256>>>(trans, pred, labels);

    rnnt_dp_kernel<<<NB, 96>>>(act_l, label_l);

    rnnt_finish_kernel<<<1, 32>>>(out);
}

// round 6
// speedup vs baseline: 2.1177x; 2.1177x over previous
#include <cuda_runtime.h>
#include <math.h>

#define NB 8
#define NT 128
#define NU 64
#define NU1 65
#define NV 512

#define NEGF (-1e30f)

// ---------------- device scratch (no allocations allowed) ----------------
__device__ __align__(16) float g_Et[NB * NT * NV];    // exp(trans - rowmax)
__device__ __align__(16) float g_Ep[NB * NU1 * NV];   // exp(pred  - rowmax)
__device__ float g_mt[NB * NT];
__device__ float g_mp[NB * NU1];
__device__ __align__(16) float g_lpb[NB * NT * NU1];  // log P(blank)  (b,t,u)
__device__ __align__(16) float g_lpl[NB * NT * NU];   // log P(label)  (b,t,u)
__device__ float g_cost[NB];
__device__ unsigned int g_done;

// ---------------- kernel 1: row max + exp (vectorized) ----------------
__global__ void __launch_bounds__(128)
rnnt_prep_kernel(const float* __restrict__ trans,
                 const float* __restrict__ pred) {
    if (blockIdx.x == 0 && threadIdx.x == 0) g_done = 0;  // reset dp counter
    int row = blockIdx.x;
    const float* src;
    float* dst;
    float* mdst;
    if (row < NB * NT) {
        src = trans + (size_t)row * NV;
        dst = g_Et + (size_t)row * NV;
        mdst = g_mt + row;
    } else {
        int r = row - NB * NT;
        src = pred + (size_t)r * NV;
        dst = g_Ep + (size_t)r * NV;
        mdst = g_mp + r;
    }
    int tid = threadIdx.x;  // 128 threads, 4 floats each
    float4 v = ((const float4*)src)[tid];
    float m = fmaxf(fmaxf(v.x, v.y), fmaxf(v.z, v.w));
#pragma unroll
    for (int o = 16; o > 0; o >>= 1)
        m = fmaxf(m, __shfl_xor_sync(0xffffffffu, m, o));
    __shared__ float sm[4];
    if ((tid & 31) == 0) sm[tid >> 5] = m;
    __syncthreads();
    m = fmaxf(fmaxf(sm[0], sm[1]), fmaxf(sm[2], sm[3]));
    if (tid == 0) *mdst = m;
    float4 e;
    e.x = __expf(v.x - m);
    e.y = __expf(v.y - m);
    e.z = __expf(v.z - m);
    e.w = __expf(v.w - m);
    ((float4*)dst)[tid] = e;
}

// ---------------- kernel 2: batched Et @ Ep^T + epilogue ----------------
#define TK 32
__global__ void __launch_bounds__(256)
rnnt_joint_kernel(const float* __restrict__ trans,
                  const float* __restrict__ pred,
                  const int* __restrict__ labels) {
    int b  = blockIdx.z;
    int t0 = blockIdx.y * 16;
    int u0 = blockIdx.x * 16;

    __shared__ float As[16][TK + 4];  // stride 36 floats: conflict-free LDS.128
    __shared__ float Bs[16][TK + 4];

    int tid = threadIdx.x;            // 256 threads
    int tx = tid & 15;                // u within tile
    int ty = tid >> 4;                // t within tile

    const float* __restrict__ Et = g_Et + ((size_t)(b * NT + t0)) * NV;
    const float* __restrict__ Ep = g_Ep + ((size_t)(b * NU1)) * NV;

    float acc = 0.f;
    for (int k0 = 0; k0 < NV; k0 += TK) {
#pragma unroll
        for (int i = 0; i < 2; i++) {
            int idx = tid + i * 256;
            int r = idx >> 5;
            int c = idx & 31;
            As[r][c] = Et[(size_t)r * NV + k0 + c];
            int uu = u0 + r;
            Bs[r][c] = (uu < NU1) ? Ep[(size_t)uu * NV + k0 + c] : 0.f;
        }
        __syncthreads();
        const float4* a4 = (const float4*)(&As[ty][0]);
        const float4* b4 = (const float4*)(&Bs[tx][0]);
#pragma unroll
        for (int k = 0; k < TK / 4; k++) {
            float4 av = a4[k];
            float4 bv = b4[k];
            acc += av.x * bv.x + av.y * bv.y + av.z * bv.z + av.w * bv.w;
        }
        __syncthreads();
    }

    int t = t0 + ty;
    int u = u0 + tx;
    if (u < NU1) {
        float lse = logf(acc) + g_mt[b * NT + t] + g_mp[b * NU1 + u];
        const float* trow = trans + ((size_t)(b * NT + t)) * NV;
        const float* prow = pred + ((size_t)(b * NU1 + u)) * NV;
        g_lpb[(b * NT + t) * NU1 + u] = trow[0] + prow[0] - lse;
        if (u < NU) {
            int lab = labels[b * NU + u];
            g_lpl[(b * NT + t) * NU + u] = trow[lab] + prow[lab] - lse;
        }
    }
}

// ---------------- kernel 3: alpha DP, register wavefront, 2 t-chunks -----
// alpha recursion depends only on diagonal d-1 -> alpha lives in registers.
// LPB/LPL staged per 64-row t-chunk with row stride 66 (odd lane stride ->
// conflict-free diagonal LDS gathers). ~34 KB static smem, no attribute.
#define CH 64      // t-rows per chunk
#define SST 66     // padded smem row stride (floats)

__device__ __forceinline__ float lae(float a, float c) {
    float mx = fmaxf(a, c);
    float mn = fminf(a, c);
    return mx + __logf(1.0f + __expf(mn - mx));
}

__global__ void __launch_bounds__(128)
rnnt_dp_kernel(const int* __restrict__ act_lens,
               const int* __restrict__ label_lens,
               float* __restrict__ out) {
    int b = blockIdx.x;
    __shared__ float sLPB[CH * SST];   // lpb rows [base_b .. base_b+63]
    __shared__ float sLPL[CH * SST];   // lpl rows [base_l .. base_l+63]
    __shared__ float bnd[2][4];        // cross-warp boundary, double-buffered
    __shared__ float sFin;             // captured alpha(te, ue)

    int tid  = threadIdx.x;            // 128 threads; u = tid (active u <= 64)
    int lane = tid & 31;
    int w    = tid >> 5;
    int u    = tid;

    int te = act_lens[b] - 1;          // uniform loads (broadcast)
    int ue = label_lens[b];

    float a = 0.f;                     // thread u's rolling alpha register

    for (int chunk = 0; chunk < 2; chunk++) {
        int t0     = chunk * CH;
        int base_b = (chunk == 0) ? 0 : (t0 - 1);
        int base_l = t0;

        // ---- stage this chunk's tables (coalesced-ish, conflict-free STS) --
        {
            const float* gB = g_lpb + ((size_t)(b * NT + base_b)) * NU1;
            for (int i = tid; i < CH * NU1; i += 128) {
                int r = i / NU1, c = i - r * NU1;
                sLPB[r * SST + c] = gB[(size_t)r * NU1 + c];
            }
            const float* gL = g_lpl + ((size_t)(b * NT + base_l)) * NU;
            for (int i = tid; i < CH * NU; i += 128) {
                int r = i >> 6, c = i & 63;
                sLPL[r * SST + c] = gL[(size_t)(r << 6) + c];
            }
        }
        __syncthreads();

        // ---- wavefront: local diagonals dl; cell t = t0 + dl - u ----------
        int dl_lo = (chunk == 0) ? 1 : 0;   // chunk 0: (0,0) seeded a=0
        for (int dl = dl_lo; dl <= CH - 1 + NU1 - 1; dl++) {
            int p = dl & 1;
            // neighbor's alpha from diagonal dl-1
            float up = __shfl_up_sync(0xffffffffu, a, 1);
            if (lane == 0 && w > 0) up = bnd[p ^ 1][w - 1];

            int t = t0 + dl - u;
            if (u <= NU - 0 && u < NU1 + 0 && t >= t0 && t <= t0 + CH - 1) {
                float pa = (t >= 1)
                    ? a + sLPB[(t - 1 - base_b) * SST + u] : NEGF;
                float pb = (u >= 1)
                    ? up + sLPL[(t - base_l) * SST + (u - 1)] : NEGF;
                a = lae(pa, pb);
                if (t == te && u == ue) sFin = a;
            }
            if (lane == 31) bnd[p][w] = a;
            __syncthreads();
        }
        // barrier above also protects table overwrite in next chunk
    }

    // ---- per-batch cost + deterministic last-CTA reduction ---------------
    if (tid == 0) {
        float lpb_fin = g_lpb[(size_t)(b * NT + te) * NU1 + ue];
        g_cost[b] = -(sFin + lpb_fin);
        __threadfence();
        unsigned int prev = atomicAdd(&g_done, 1u);
        if (prev == NB - 1) {  // last CTA: fixed-order sum -> deterministic
            float s = 0.f;
            volatile float* vc = g_cost;
            for (int i = 0; i < NB; i++) s += vc[i];
            out[0] = s;
        }
    }
}

extern "C" void kernel_launch(void* const* d_in, const int* in_sizes, int n_in,
                              void* d_out, int out_size) {
    const float* trans   = (const float*)d_in[0];  // (B,T,V)
    const float* pred    = (const float*)d_in[1];  // (B,U1,V)
    const int*   labels  = (const int*)d_in[2];    // (B,U)
    const int*   act_l   = (const int*)d_in[3];    // (B,)
    const int*   label_l = (const int*)d_in[4];    // (B,)
    float*       out     = (float*)d_out;

    rnnt_prep_kernel<<<NB * NT + NB * NU1, 128>>>(trans, pred);

    dim3 jg((NU1 + 15) / 16, NT / 16, NB);  // (5, 8, 8)
    rnnt_joint_kernel<<<jg, 256>>>(trans, pred, labels);

    rnnt_dp_kernel<<<NB, 128>>>(act_l, label_l, out);
}

// round 8
// speedup vs baseline: 2.2665x; 1.0702x over previous
#include <cuda_runtime.h>
#include <math.h>

#define NB 8
#define NT 128
#define NU 64
#define NU1 65
#define NV 512
#define NEGF (-1e30f)

#define UT 5                      // u tiles (16 wide) covering 65
#define TT 8                      // t tiles
#define TILES_PER_B (UT * TT)     // 40
#define JOINT_CTAS (NB * TILES_PER_B)  // 320
#define TK 32

// ---------------- device scratch (no allocations allowed) ----------------
__device__ __align__(16) float g_lpb[NB * NT * NU1];  // log P(blank)  (b,t,u)
__device__ __align__(16) float g_lpl[NB * NT * NU];   // log P(label)  (b,t,u)
__device__ float g_cost[NB];
__device__ unsigned int g_ready[NB];   // tiles finished per batch (self-reset)
__device__ unsigned int g_done;        // dp CTAs finished (self-reset)

__device__ __forceinline__ float lae(float a, float c) {
    float mx = fmaxf(a, c);
    float mn = fminf(a, c);
    return mx + __logf(1.0f + __expf(mn - mx));
}

// dp staging: 64-row t-chunks, padded stride 66 (odd -> conflict-free diagonals)
#define CH 64
#define SST 66

__global__ void __launch_bounds__(256)
rnnt_fused_kernel(const float* __restrict__ trans,
                  const float* __restrict__ pred,
                  const int* __restrict__ labels,
                  const int* __restrict__ act_lens,
                  const int* __restrict__ label_lens,
                  float* __restrict__ out) {
    int tid = threadIdx.x;

    if (blockIdx.x < JOINT_CTAS) {
        // ================= JOINT path: on-the-fly softmax GEMM =============
        __shared__ float As[16][TK + 4];
        __shared__ float Bs[16][TK + 4];
        __shared__ float mA[16], mB[16];

        int blk = blockIdx.x;
        int b   = blk / TILES_PER_B;
        int rem = blk - b * TILES_PER_B;
        int t0  = (rem / UT) * 16;
        int u0  = (rem % UT) * 16;

        const float* Tb = trans + ((size_t)(b * NT + t0)) * NV;
        const float* Pb = pred + ((size_t)b * NU1) * NV;

        // ---- phase A: row maxes (32 rows, 8 threads/row) ----
        {
            int r   = tid >> 3;      // 0..31
            int sub = tid & 7;
            float m = NEGF;
            const float* rowp = 0;
            if (r < 16) {
                rowp = Tb + (size_t)r * NV;
            } else {
                int uu = u0 + (r - 16);
                if (uu < NU1) rowp = Pb + (size_t)uu * NV;
            }
            if (rowp) {
                const float4* p4 = (const float4*)rowp;
                for (int k = sub; k < NV / 4; k += 8) {
                    float4 v = p4[k];
                    m = fmaxf(m, fmaxf(fmaxf(v.x, v.y), fmaxf(v.z, v.w)));
                }
            }
#pragma unroll
            for (int o = 4; o > 0; o >>= 1)
                m = fmaxf(m, __shfl_xor_sync(0xffffffffu, m, o));
            if (sub == 0) {
                if (r < 16) mA[r] = m;
                else        mB[r - 16] = m;
            }
        }
        __syncthreads();

        // ---- phase B: tiled dot of exp'd rows ----
        int tx = tid & 15;   // u in tile
        int ty = tid >> 4;   // t in tile
        float acc = 0.f;
        for (int k0 = 0; k0 < NV; k0 += TK) {
#pragma unroll
            for (int i = 0; i < 2; i++) {
                int idx = tid + i * 256;
                int rr = idx >> 5;
                int cc = idx & 31;
                As[rr][cc] = __expf(Tb[(size_t)rr * NV + k0 + cc] - mA[rr]);
                int uu = u0 + rr;
                Bs[rr][cc] = (uu < NU1)
                    ? __expf(Pb[(size_t)uu * NV + k0 + cc] - mB[rr]) : 0.f;
            }
            __syncthreads();
            const float4* a4 = (const float4*)(&As[ty][0]);
            const float4* b4 = (const float4*)(&Bs[tx][0]);
#pragma unroll
            for (int k = 0; k < TK / 4; k++) {
                float4 av = a4[k];
                float4 bv = b4[k];
                acc += av.x * bv.x + av.y * bv.y + av.z * bv.z + av.w * bv.w;
            }
            __syncthreads();
        }

        // ---- epilogue: lse + gather blank/label logits ----
        int t = t0 + ty;
        int u = u0 + tx;
        if (u < NU1) {
            float lse = logf(acc) + mA[ty] + mB[tx];
            const float* trow = Tb + (size_t)ty * NV;
            const float* prow = Pb + (size_t)u * NV;
            g_lpb[(b * NT + t) * NU1 + u] = trow[0] + prow[0] - lse;
            if (u < NU) {
                int lab = labels[b * NU + u];
                g_lpl[(b * NT + t) * NU + u] = trow[lab] + prow[lab] - lse;
            }
        }
        __syncthreads();
        if (tid == 0) {
            __threadfence();                 // release lpb/lpl
            atomicAdd(&g_ready[b], 1u);
        }
    } else {
        // ================= DP path: per-batch alpha wavefront ==============
        __shared__ float sLPB[CH * SST];
        __shared__ float sLPL[CH * SST];
        __shared__ float bnd[2][8];
        __shared__ float sFin;

        int b = blockIdx.x - JOINT_CTAS;
        int lane = tid & 31;
        int w    = tid >> 5;
        int u    = tid;

        // wait until this batch's 40 tiles are published (grid is single-wave
        // resident: 328 CTAs << thread/smem capacity, so producers always run)
        if (tid == 0) {
            volatile unsigned int* rdy = &g_ready[b];
            while (*rdy < (unsigned)TILES_PER_B) __nanosleep(128);
            __threadfence();                 // acquire lpb/lpl
        }
        __syncthreads();

        int te = act_lens[b] - 1;
        int ue = label_lens[b];

        float a = 0.f;   // rolling alpha register for this thread's u

        for (int chunk = 0; chunk < 2; chunk++) {
            int t0c    = chunk * CH;
            int base_b = (chunk == 0) ? 0 : (t0c - 1);
            int base_l = t0c;

            // stage tables (L2-coherent loads; writers are other SMs)
            {
                const float* gB = g_lpb + ((size_t)(b * NT + base_b)) * NU1;
                for (int i = tid; i < CH * NU1; i += 256) {
                    int r = i / NU1, c = i - r * NU1;
                    sLPB[r * SST + c] = __ldcg(gB + i);
                }
                const float* gL = g_lpl + ((size_t)(b * NT + base_l)) * NU;
                for (int i = tid; i < CH * NU; i += 256) {
                    sLPL[(i >> 6) * SST + (i & 63)] = __ldcg(gL + i);
                }
            }
            __syncthreads();

            int dl_lo = (chunk == 0) ? 1 : 0;   // (0,0) seeded a=0
            for (int dl = dl_lo; dl <= CH - 1 + NU1 - 1; dl++) {
                int p = dl & 1;
                float up = __shfl_up_sync(0xffffffffu, a, 1);
                if (lane == 0 && w > 0) up = bnd[p ^ 1][w - 1];

                int t = t0c + dl - u;
                if (u < NU1 && t >= t0c && t <= t0c + CH - 1) {
                    float pa = (t >= 1)
                        ? a + sLPB[(t - 1 - base_b) * SST + u] : NEGF;
                    float pb = (u >= 1)
                        ? up + sLPL[(t - base_l) * SST + (u - 1)] : NEGF;
                    a = lae(pa, pb);
                    if (t == te && u == ue) sFin = a;
                }
                if (lane == 31) bnd[p][w] = a;
                __syncthreads();
            }
        }

        if (tid == 0) {
            float lpb_fin = __ldcg(&g_lpb[(size_t)(b * NT + te) * NU1 + ue]);
            g_cost[b] = -(sFin + lpb_fin);
            __threadfence();
            unsigned int prev = atomicAdd(&g_done, 1u);
            if (prev == NB - 1) {   // last dp CTA: fixed-order deterministic sum
                float s = 0.f;
                volatile float* vc = g_cost;
                for (int i = 0; i < NB; i++) s += vc[i];
                out[0] = s;
                g_done = 0;         // self-reset for next invocation/replay
            }
            g_ready[b] = 0;         // self-reset (all 40 tiles were observed)
        }
    }
}

extern "C" void kernel_launch(void* const* d_in, const int* in_sizes, int n_in,
                              void* d_out, int out_size) {
    const float* trans   = (const float*)d_in[0];  // (B,T,V)
    const float* pred    = (const float*)d_in[1];  // (B,U1,V)
    const int*   labels  = (const int*)d_in[2];    // (B,U)
    const int*   act_l   = (const int*)d_in[3];    // (B,)
    const int*   label_l = (const int*)d_in[4];    // (B,)
    float*       out     = (float*)d_out;

    rnnt_fused_kernel<<<JOINT_CTAS + NB, 256>>>(trans, pred, labels,
                                                act_l, label_l, out);
}